// round 16
// baseline (speedup 1.0000x reference)
#include <cuda_runtime.h>
#include <cuda_bf16.h>
#include <cstdint>
#include <math.h>

#define BB 8
#define TT 32
#define NN 1024
#define DIN 64
#define DR 128
#define DT_C 0.25f
typedef __nv_bfloat16 bf16;

#define OW0 0
#define OW1 16384
#define OWOUT 32768
#define OWZ 49152
#define OWR 73728
#define OWH 98304
#define OWO 122880

// ------------------------- device scratch (no allocs) ----------------------
__device__ bf16 g_Ahi[(size_t)BB*NN*NN];
__device__ bf16 g_Alo[(size_t)BB*NN*NN];
__device__ bf16 g_Xhi[(size_t)BB*TT*NN*DIN];
__device__ bf16 g_Xlo[(size_t)BB*TT*NN*DIN];
__device__ bf16 g_AXhi[(size_t)TT*BB*NN*DIN];
__device__ bf16 g_AXlo[(size_t)TT*BB*NN*DIN];
__device__ float g_H[BB*NN*DR];
__device__ bf16 g_Hhi[BB*NN*DR], g_Hlo[BB*NN*DR];
__device__ float g_HV1[BB*NN*DR];
__device__ float g_G1[BB*NN*DR];
__device__ bf16 g_Uahi[BB*NN*DR], g_Ualo[BB*NN*DR];
__device__ bf16 g_Ubhi[BB*NN*DR], g_Ublo[BB*NN*DR];
__device__ bf16 g_RHhi[BB*NN*DR], g_RHlo[BB*NN*DR];
__device__ float g_Z[BB*NN*DR];
__device__ float g_OBS[TT*BB];
__device__ bf16 g_Whi[131072], g_Wlo[131072];
__device__ unsigned g_bar;

// ----------------------------- PTX helpers ---------------------------------
__device__ __forceinline__ unsigned smem_u32(const void* p) {
    unsigned a;
    asm("{ .reg .u64 t; cvta.to.shared.u64 t, %1; cvt.u32.u64 %0, t; }"
        : "=r"(a) : "l"(p));
    return a;
}
__device__ __forceinline__ void ldm_x4(unsigned& r0, unsigned& r1,
                                       unsigned& r2, unsigned& r3, unsigned a) {
    asm volatile("ldmatrix.sync.aligned.m8n8.x4.shared.b16 {%0,%1,%2,%3}, [%4];"
                 : "=r"(r0), "=r"(r1), "=r"(r2), "=r"(r3) : "r"(a));
}
__device__ __forceinline__ void ldm_x2t(unsigned& r0, unsigned& r1, unsigned a) {
    asm volatile("ldmatrix.sync.aligned.m8n8.x2.trans.shared.b16 {%0,%1}, [%2];"
                 : "=r"(r0), "=r"(r1) : "r"(a));
}
__device__ __forceinline__ void ldm_x4t(unsigned& r0, unsigned& r1,
                                        unsigned& r2, unsigned& r3, unsigned a) {
    asm volatile("ldmatrix.sync.aligned.m8n8.x4.trans.shared.b16 {%0,%1,%2,%3}, [%4];"
                 : "=r"(r0), "=r"(r1), "=r"(r2), "=r"(r3) : "r"(a));
}
__device__ __forceinline__ void mma_bf16(float* c, const unsigned* A, const unsigned* B) {
    asm volatile(
        "mma.sync.aligned.m16n8k16.row.col.f32.bf16.bf16.f32 "
        "{%0,%1,%2,%3}, {%4,%5,%6,%7}, {%8,%9}, {%0,%1,%2,%3};"
        : "+f"(c[0]), "+f"(c[1]), "+f"(c[2]), "+f"(c[3])
        : "r"(A[0]), "r"(A[1]), "r"(A[2]), "r"(A[3]), "r"(B[0]), "r"(B[1]));
}
__device__ __forceinline__ void cp16(unsigned s, const void* g) {
    asm volatile("cp.async.cg.shared.global [%0], [%1], 16;" :: "r"(s), "l"(g));
}
__device__ __forceinline__ void cp_commit() { asm volatile("cp.async.commit_group;"); }
template<int N> __device__ __forceinline__ void cp_wait() {
    asm volatile("cp.async.wait_group %0;" :: "n"(N));
}
__device__ __forceinline__ void store_hilo(bf16* hi, bf16* lo, size_t idx,
                                           float a, float b) {
    __nv_bfloat162 h = __floats2bfloat162_rn(a, b);
    *(unsigned*)(hi + idx) = *reinterpret_cast<unsigned*>(&h);
    __nv_bfloat162 l = __floats2bfloat162_rn(a - __bfloat162float(h.x),
                                             b - __bfloat162float(h.y));
    *(unsigned*)(lo + idx) = *reinterpret_cast<unsigned*>(&l);
}
__device__ __forceinline__ float sigm(float x) {
    return __fdividef(1.f, 1.f + __expf(-x));
}
__device__ __forceinline__ float ftanh(float x) {
    return 1.f - __fdividef(2.f, __expf(2.f * x) + 1.f);
}
// grid-wide barrier: release-arrive, tid0 spins, acquire, CTA release.
__device__ __forceinline__ void grid_bar(unsigned target, int tid) {
    __syncthreads();
    if (tid == 0) {
        __threadfence();
        atomicAdd(&g_bar, 1u);
        while (*(volatile unsigned*)&g_bar < target)
            asm volatile("nanosleep.u32 64;");
        __threadfence();
    }
    __syncthreads();
}

// epilogue smem layout (bf16 elements)
#define AP2 200
#define ACT_HI 0
#define ACT_LO 12800
#define WBOFF 25600
#define WBSZ 17408
#define PARK_HI 60416
#define PARK_LO 73216

// pipelined single-W epilogue GEMM (3-product, 2 W buffers)
template<int NBE>
__device__ __forceinline__ void epi3(
    bf16* sm, unsigned sbase, int aHi, int aLo, int Kd, int WP,
    const bf16* Whi, const bf16* Wlo, int Dout,
    int tid, int lane, int m0w, int n0e, float (&e)[2][NBE][4])
{
    #pragma unroll
    for (int i = 0; i < 2; i++)
        #pragma unroll
        for (int j = 0; j < NBE; j++)
            #pragma unroll
            for (int q = 0; q < 4; q++) e[i][j][q] = 0.f;
    const int du4 = Dout / 8;
    auto stW = [&](int k0, int wb) {
        const int base = WBOFF + wb * WBSZ;
        for (int it = tid; it < 64 * du4; it += 256) {
            int r = it / du4, c = (it % du4) * 8;
            cp16(sbase + 2u * (base + r * WP + c), Whi + (size_t)(k0 + r) * Dout + c);
            cp16(sbase + 2u * (base + 64 * WP + r * WP + c),
                 Wlo + (size_t)(k0 + r) * Dout + c);
        }
        cp_commit();
    };
    const int NC = Kd / 64;
    __syncthreads();
    stW(0, 0);
    for (int c = 0; c < NC; c++) {
        cp_wait<0>();
        __syncthreads();
        if (c + 1 < NC) stW((c + 1) * 64, (c + 1) & 1);
        const int wb = WBOFF + (c & 1) * WBSZ;
        const int wl = wb + 64 * WP;
        #pragma unroll
        for (int ks = 0; ks < 4; ks++) {
            const int kk = ks * 16;
            unsigned ah[2][4], al[2][4];
            #pragma unroll
            for (int mi = 0; mi < 2; mi++) {
                unsigned row = m0w + mi * 16 + (lane & 15);
                unsigned col = c * 64 + kk + (lane >> 4) * 8;
                ldm_x4(ah[mi][0], ah[mi][1], ah[mi][2], ah[mi][3],
                       sbase + 2u * (aHi + row * AP2 + col));
                ldm_x4(al[mi][0], al[mi][1], al[mi][2], al[mi][3],
                       sbase + 2u * (aLo + row * AP2 + col));
            }
            unsigned bh[NBE][2], bl[NBE][2];
            if constexpr (NBE >= 2) {
                #pragma unroll
                for (int ni = 0; ni < NBE; ni += 2) {
                    unsigned row = kk + (lane & 15);
                    unsigned col = n0e + ni * 8 + (lane >> 4) * 8;
                    ldm_x4t(bh[ni][0], bh[ni][1], bh[ni+1][0], bh[ni+1][1],
                            sbase + 2u * (wb + row * WP + col));
                    ldm_x4t(bl[ni][0], bl[ni][1], bl[ni+1][0], bl[ni+1][1],
                            sbase + 2u * (wl + row * WP + col));
                }
            } else {
                unsigned row = kk + (lane & 15);
                ldm_x2t(bh[0][0], bh[0][1], sbase + 2u * (wb + row * WP + n0e));
                ldm_x2t(bl[0][0], bl[0][1], sbase + 2u * (wl + row * WP + n0e));
            }
            #pragma unroll
            for (int mi = 0; mi < 2; mi++)
                #pragma unroll
                for (int ni = 0; ni < NBE; ni++) {
                    mma_bf16(e[mi][ni], ah[mi], bh[ni]);
                    mma_bf16(e[mi][ni], ah[mi], bl[ni]);
                    mma_bf16(e[mi][ni], al[mi], bh[ni]);
                }
        }
    }
}

// dual-W epilogue GEMM (Z and R gates share the act tile; Dout=128)
__device__ __forceinline__ void epi3dual(
    bf16* sm, unsigned sbase, int Kd,
    const bf16* W0h, const bf16* W0l, const bf16* W1h, const bf16* W1l,
    int tid, int lane, int m0w, int n0e,
    float (&e0)[2][4][4], float (&e1)[2][4][4])
{
    #pragma unroll
    for (int i = 0; i < 2; i++)
        #pragma unroll
        for (int j = 0; j < 4; j++)
            #pragma unroll
            for (int q = 0; q < 4; q++) { e0[i][j][q] = 0.f; e1[i][j][q] = 0.f; }
    constexpr int WP = 136;
    auto stW = [&](const bf16* Whi, const bf16* Wlo, int k0, int wb) {
        const int base = WBOFF + wb * WBSZ;
        for (int it = tid; it < 64 * 16; it += 256) {
            int r = it / 16, c = (it % 16) * 8;
            cp16(sbase + 2u * (base + r * WP + c), Whi + (size_t)(k0 + r) * 128 + c);
            cp16(sbase + 2u * (base + 64 * WP + r * WP + c),
                 Wlo + (size_t)(k0 + r) * 128 + c);
        }
    };
    const int NC = Kd / 64;
    for (int c = 0; c < NC; c++) {
        __syncthreads();
        stW(W0h, W0l, c * 64, 0);
        stW(W1h, W1l, c * 64, 1);
        cp_commit();
        cp_wait<0>();
        __syncthreads();
        #pragma unroll
        for (int ks = 0; ks < 4; ks++) {
            const int kk = ks * 16;
            unsigned ah[2][4], al[2][4];
            #pragma unroll
            for (int mi = 0; mi < 2; mi++) {
                unsigned row = m0w + mi * 16 + (lane & 15);
                unsigned col = c * 64 + kk + (lane >> 4) * 8;
                ldm_x4(ah[mi][0], ah[mi][1], ah[mi][2], ah[mi][3],
                       sbase + 2u * (ACT_HI + row * AP2 + col));
                ldm_x4(al[mi][0], al[mi][1], al[mi][2], al[mi][3],
                       sbase + 2u * (ACT_LO + row * AP2 + col));
            }
            #pragma unroll
            for (int w = 0; w < 2; w++) {
                const int wb = WBOFF + w * WBSZ, wl = wb + 64 * WP;
                unsigned bh[4][2], bl[4][2];
                #pragma unroll
                for (int ni = 0; ni < 4; ni += 2) {
                    unsigned row = kk + (lane & 15);
                    unsigned col = n0e + ni * 8 + (lane >> 4) * 8;
                    ldm_x4t(bh[ni][0], bh[ni][1], bh[ni+1][0], bh[ni+1][1],
                            sbase + 2u * (wb + row * WP + col));
                    ldm_x4t(bl[ni][0], bl[ni][1], bl[ni+1][0], bl[ni+1][1],
                            sbase + 2u * (wl + row * WP + col));
                }
                #pragma unroll
                for (int mi = 0; mi < 2; mi++)
                    #pragma unroll
                    for (int ni = 0; ni < 4; ni++) {
                        float* ee = w ? e1[mi][ni] : e0[mi][ni];
                        mma_bf16(ee, ah[mi], bh[ni]);
                        mma_bf16(ee, ah[mi], bl[ni]);
                        mma_bf16(ee, al[mi], bh[ni]);
                    }
            }
        }
    }
}

template<int NBX>
__device__ __forceinline__ void frag2act(const float (&a)[2][NBX][4], bf16* sm,
                                         int hiOff, int loOff, int goff,
                                         int m0, int n0, int lane)
{
    const int g4 = lane >> 2, t4 = lane & 3;
    #pragma unroll
    for (int mi = 0; mi < 2; mi++)
        #pragma unroll
        for (int ni = 0; ni < NBX; ni++) {
            int r0 = m0 + mi * 16 + g4;
            int c  = goff + n0 + ni * 8 + t4 * 2;
            store_hilo(sm + hiOff, sm + loOff, (size_t)r0 * AP2 + c,
                       a[mi][ni][0], a[mi][ni][1]);
            store_hilo(sm + hiOff, sm + loOff, (size_t)(r0 + 8) * AP2 + c,
                       a[mi][ni][2], a[mi][ni][3]);
        }
}

// ---------------------------------------------------------------------------
// ax_kernel: AX[t,b] = A[b] @ X[b,t], bf16 hi/lo out.  grid (16,1,BB*TT)
// ---------------------------------------------------------------------------
__global__ void __launch_bounds__(256) ax_kernel(
    const bf16* __restrict__ Bhi_g, const bf16* __restrict__ Blo_g)
{
    constexpr int DN = 64;
    constexpr int AP = 72, BP = DN + 8, NB = 2;
    constexpr int A_LO = 64 * AP;
    constexpr int B_OFF = 2 * 64 * AP;
    constexpr int B_LO  = B_OFF + 64 * BP;
    constexpr int SBUF  = 2 * 64 * AP + 2 * 64 * BP;

    extern __shared__ bf16 sm[];
    const unsigned sbase = smem_u32(sm);
    const int tid = threadIdx.x, wid = tid >> 5, lane = tid & 31;
    const int mt = blockIdx.x;
    const int z  = blockIdx.z;
    const int a_idx = z / TT;
    const int cz = (z % TT) * BB + a_idx;
    const bf16* Bhi = Bhi_g + (size_t)z * NN * DN;
    const bf16* Blo = Blo_g + (size_t)z * NN * DN;
    const bf16* Ahi = g_Ahi + ((size_t)a_idx * NN + (size_t)mt * 64) * NN;
    const bf16* Alo = g_Alo + ((size_t)a_idx * NN + (size_t)mt * 64) * NN;
    const int wm = wid >> 2, wn = wid & 3;
    const int m0w = wm * 32, n0w = wn * (DN / 4);

    auto stage = [&](int ch, int buf) {
        const int k0 = ch * 64;
        const unsigned db = sbase + 2u * (unsigned)(buf * SBUF);
        #pragma unroll
        for (int it = 0; it < 2; it++) {
            int item = tid + it * 256, r = item >> 3, c = item & 7;
            cp16(db + 2u * (r * AP + c * 8),        Ahi + (size_t)r * NN + k0 + c * 8);
            cp16(db + 2u * (A_LO + r * AP + c * 8), Alo + (size_t)r * NN + k0 + c * 8);
        }
        #pragma unroll
        for (int it = 0; it < 2; it++) {
            int item = tid + it * 256, r = item / 8, c = item % 8;
            cp16(db + 2u * (B_OFF + r * BP + c * 8), Bhi + (size_t)(k0 + r) * DN + c * 8);
            cp16(db + 2u * (B_LO  + r * BP + c * 8), Blo + (size_t)(k0 + r) * DN + c * 8);
        }
        cp_commit();
    };

    float acc[2][NB][4];
    #pragma unroll
    for (int i = 0; i < 2; i++)
        #pragma unroll
        for (int j = 0; j < NB; j++)
            #pragma unroll
            for (int q = 0; q < 4; q++) acc[i][j][q] = 0.f;

    stage(0, 0); stage(1, 1);
    for (int ch = 0; ch < 16; ch++) {
        const int buf = ch % 3;
        if (ch < 15) cp_wait<1>(); else cp_wait<0>();
        __syncthreads();
        if (ch <= 13) stage(ch + 2, (ch + 2) % 3);
        const unsigned aB = sbase + 2u * (unsigned)(buf * SBUF);
        #pragma unroll
        for (int ks = 0; ks < 4; ks++) {
            const int kk = ks * 16;
            unsigned ah[2][4], al[2][4];
            #pragma unroll
            for (int mi = 0; mi < 2; mi++) {
                unsigned row = m0w + mi * 16 + (lane & 15);
                unsigned col = kk + (lane >> 4) * 8;
                ldm_x4(ah[mi][0], ah[mi][1], ah[mi][2], ah[mi][3],
                       aB + 2u * (row * AP + col));
                ldm_x4(al[mi][0], al[mi][1], al[mi][2], al[mi][3],
                       aB + 2u * (A_LO + row * AP + col));
            }
            unsigned bh[NB][2], bl[NB][2];
            {
                unsigned row = kk + (lane & 15);
                unsigned col = n0w + (lane >> 4) * 8;
                ldm_x4t(bh[0][0], bh[0][1], bh[1][0], bh[1][1],
                        aB + 2u * (B_OFF + row * BP + col));
                ldm_x4t(bl[0][0], bl[0][1], bl[1][0], bl[1][1],
                        aB + 2u * (B_LO + row * BP + col));
            }
            #pragma unroll
            for (int mi = 0; mi < 2; mi++)
                #pragma unroll
                for (int ni = 0; ni < NB; ni++) {
                    mma_bf16(acc[mi][ni], ah[mi], bh[ni]);
                    mma_bf16(acc[mi][ni], ah[mi], bl[ni]);
                    mma_bf16(acc[mi][ni], al[mi], bh[ni]);
                }
        }
    }
    const int g4 = lane >> 2, t4 = lane & 3;
    bf16* ohi = g_AXhi + (size_t)cz * NN * DIN;
    bf16* olo = g_AXlo + (size_t)cz * NN * DIN;
    #pragma unroll
    for (int mi = 0; mi < 2; mi++)
        #pragma unroll
        for (int ni = 0; ni < NB; ni++) {
            int r0 = mt * 64 + m0w + mi * 16 + g4;
            int c  = n0w + ni * 8 + t4 * 2;
            store_hilo(ohi, olo, (size_t)r0 * DN + c, acc[mi][ni][0], acc[mi][ni][1]);
            store_hilo(ohi, olo, (size_t)(r0 + 8) * DN + c, acc[mi][ni][2], acc[mi][ni][3]);
        }
}

// ---------------------------------------------------------------------------
// persist_kernel: all 130 recurrence phases, grid 128 CTAs, grid barriers.
// ---------------------------------------------------------------------------
__global__ void __launch_bounds__(256) persist_kernel(
    const float* __restrict__ b0v, const float* __restrict__ b1v,
    const float* __restrict__ bou, const float* __restrict__ bz,
    const float* __restrict__ br,  const float* __restrict__ bh,
    const float* __restrict__ bo,  float* __restrict__ out)
{
    constexpr int DN = 128;
    constexpr int AP = 72, BP = DN + 8, NB = 4;
    constexpr int A_LO = 64 * AP;
    constexpr int B_OFF = 2 * 64 * AP;
    constexpr int B_LO  = B_OFF + 64 * BP;
    constexpr int SBUF  = 2 * 64 * AP + 2 * 64 * BP;

    extern __shared__ bf16 sm[];
    const unsigned sbase = smem_u32(sm);
    const int tid = threadIdx.x, wid = tid >> 5, lane = tid & 31;
    const int mt = blockIdx.x & 15;
    const int z  = blockIdx.x >> 4;
    const bf16* Ahi = g_Ahi + ((size_t)z * NN + (size_t)mt * 64) * NN;
    const bf16* Alo = g_Alo + ((size_t)z * NN + (size_t)mt * 64) * NN;
    const int wm = wid >> 2, wn = wid & 3;
    const int m0w = wm * 32, n0w = wn * 32;
    const int g4 = lane >> 2, t4 = lane & 3;
    const int gr0 = mt * 64;
    const int n0e = wn * 32;
    unsigned bartg = 0;

    auto stageA = [&](int ch, int buf) {
        const int k0 = ch * 64;
        const unsigned db = sbase + 2u * (unsigned)(buf * SBUF);
        #pragma unroll
        for (int it = 0; it < 2; it++) {
            int item = tid + it * 256, r = item >> 3, c = item & 7;
            cp16(db + 2u * (r * AP + c * 8),        Ahi + (size_t)r * NN + k0 + c * 8);
            cp16(db + 2u * (A_LO + r * AP + c * 8), Alo + (size_t)r * NN + k0 + c * 8);
        }
    };

    for (int k = 0; k < 33; k++) {
        const int t = k - 1;
        for (int p = 0; p < 4; p++) {
            if (p == 3 && !(t >= 0 && t < TT - 1)) break;
            const bf16 *Bhi, *Blo;
            if (p == 0)      { Bhi = g_Hhi;  Blo = g_Hlo;  }
            else if (p == 1) { Bhi = g_Uahi; Blo = g_Ualo; }
            else if (p == 2) { Bhi = g_Ubhi; Blo = g_Ublo; }
            else             { Bhi = g_RHhi; Blo = g_RHlo; }
            Bhi += (size_t)z * NN * DN;
            Blo += (size_t)z * NN * DN;

            auto stageB = [&](int ch, int buf) {
                const int k0 = ch * 64;
                const unsigned db = sbase + 2u * (unsigned)(buf * SBUF);
                #pragma unroll
                for (int it = 0; it < 4; it++) {
                    int item = tid + it * 256, r = item / 16, c = item % 16;
                    cp16(db + 2u * (B_OFF + r * BP + c * 8),
                         Bhi + (size_t)(k0 + r) * DN + c * 8);
                    cp16(db + 2u * (B_LO + r * BP + c * 8),
                         Blo + (size_t)(k0 + r) * DN + c * 8);
                }
            };

            float acc[2][NB][4];
            #pragma unroll
            for (int i = 0; i < 2; i++)
                #pragma unroll
                for (int j = 0; j < NB; j++)
                    #pragma unroll
                    for (int q = 0; q < 4; q++) acc[i][j][q] = 0.f;

            __syncthreads();                      // epi smem reuse guard
            stageA(0, 0);
            stageA(1, 1);
            grid_bar(++bartg * 128u, tid);        // B operand valid grid-wide
            stageB(0, 0); cp_commit();
            stageB(1, 1); cp_commit();

            for (int ch = 0; ch < 16; ch++) {
                const int buf = ch % 3;
                if (ch < 15) cp_wait<1>(); else cp_wait<0>();
                __syncthreads();
                if (ch <= 13) { stageA(ch + 2, (ch + 2) % 3);
                                stageB(ch + 2, (ch + 2) % 3); cp_commit(); }
                const unsigned aB = sbase + 2u * (unsigned)(buf * SBUF);
                #pragma unroll
                for (int ks = 0; ks < 4; ks++) {
                    const int kk = ks * 16;
                    unsigned ah[2][4], al[2][4];
                    #pragma unroll
                    for (int mi = 0; mi < 2; mi++) {
                        unsigned row = m0w + mi * 16 + (lane & 15);
                        unsigned col = kk + (lane >> 4) * 8;
                        ldm_x4(ah[mi][0], ah[mi][1], ah[mi][2], ah[mi][3],
                               aB + 2u * (row * AP + col));
                        ldm_x4(al[mi][0], al[mi][1], al[mi][2], al[mi][3],
                               aB + 2u * (A_LO + row * AP + col));
                    }
                    unsigned bhx[NB][2], blx[NB][2];
                    #pragma unroll
                    for (int ni = 0; ni < NB; ni += 2) {
                        unsigned row = kk + (lane & 15);
                        unsigned col = n0w + ni * 8 + (lane >> 4) * 8;
                        ldm_x4t(bhx[ni][0], bhx[ni][1], bhx[ni+1][0], bhx[ni+1][1],
                                aB + 2u * (B_OFF + row * BP + col));
                        ldm_x4t(blx[ni][0], blx[ni][1], blx[ni+1][0], blx[ni+1][1],
                                aB + 2u * (B_LO + row * BP + col));
                    }
                    #pragma unroll
                    for (int mi = 0; mi < 2; mi++)
                        #pragma unroll
                        for (int ni = 0; ni < NB; ni++) {
                            mma_bf16(acc[mi][ni], ah[mi], bhx[ni]);
                            mma_bf16(acc[mi][ni], ah[mi], blx[ni]);
                            mma_bf16(acc[mi][ni], al[mi], bhx[ni]);
                        }
                }
            }
            __syncthreads();                      // stage buffers dead

            // ---------------- epilogue ----------------
            if (p <= 1) {                         // U' = tanh(G@W + b)
                if (p == 0) {                     // also persist G1 = A@H
                    #pragma unroll
                    for (int mi = 0; mi < 2; mi++)
                        #pragma unroll
                        for (int ni = 0; ni < 4; ni++) {
                            int c = n0w + ni * 8 + t4 * 2;
                            size_t i0 = ((size_t)z * NN + gr0 + m0w + mi * 16 + g4) * DR + c;
                            *(float2*)(g_G1 + i0) = make_float2(acc[mi][ni][0], acc[mi][ni][1]);
                            *(float2*)(g_G1 + i0 + (size_t)8 * DR) =
                                make_float2(acc[mi][ni][2], acc[mi][ni][3]);
                        }
                }
                frag2act<4>(acc, sm, ACT_HI, ACT_LO, 0, m0w, n0w, lane);
                float e[2][4][4];
                epi3<4>(sm, sbase, ACT_HI, ACT_LO, 128, 136,
                        g_Whi + (p == 0 ? OW0 : OW1), g_Wlo + (p == 0 ? OW0 : OW1),
                        128, tid, lane, m0w, n0e, e);
                const float* bb = (p == 0) ? b0v : b1v;
                bf16* ohi = (p == 0) ? g_Uahi : g_Ubhi;
                bf16* olo = (p == 0) ? g_Ualo : g_Ublo;
                #pragma unroll
                for (int mi = 0; mi < 2; mi++)
                    #pragma unroll
                    for (int ni = 0; ni < 4; ni++) {
                        int c = n0e + ni * 8 + t4 * 2;
                        float2 bv = *(const float2*)(bb + c);
                        size_t i0 = ((size_t)z * NN + gr0 + m0w + mi * 16 + g4) * DR + c;
                        size_t i1 = i0 + (size_t)8 * DR;
                        store_hilo(ohi, olo, i0, ftanh(e[mi][ni][0] + bv.x),
                                               ftanh(e[mi][ni][1] + bv.y));
                        store_hilo(ohi, olo, i1, ftanh(e[mi][ni][2] + bv.x),
                                               ftanh(e[mi][ni][3] + bv.y));
                    }
            } else if (p == 2) {                  // HV1 + gates + head
                const bool do_gates = (t >= 0 && t < TT - 1);
                const bool do_head  = (t >= 1);
                float* of32 = (t < 0) ? g_H : g_HV1;
                frag2act<4>(acc, sm, ACT_HI, ACT_LO, 0, m0w, n0w, lane);
                float e[2][4][4];
                epi3<4>(sm, sbase, ACT_HI, ACT_LO, 128, 136,
                        g_Whi + OWOUT, g_Wlo + OWOUT, 128, tid, lane, m0w, n0e, e);
                #pragma unroll
                for (int mi = 0; mi < 2; mi++)
                    #pragma unroll
                    for (int ni = 0; ni < 4; ni++) {
                        int c = n0e + ni * 8 + t4 * 2;
                        float2 bv = *(const float2*)(bou + c);
                        size_t i0 = ((size_t)z * NN + gr0 + m0w + mi * 16 + g4) * DR + c;
                        size_t i1 = i0 + (size_t)8 * DR;
                        float2 h0 = *(const float2*)(g_H + i0);
                        float2 h1 = *(const float2*)(g_H + i1);
                        float v0 = h0.x + (e[mi][ni][0] + bv.x) * DT_C;
                        float v1 = h0.y + (e[mi][ni][1] + bv.y) * DT_C;
                        float v2 = h1.x + (e[mi][ni][2] + bv.x) * DT_C;
                        float v3 = h1.y + (e[mi][ni][3] + bv.y) * DT_C;
                        *(float2*)(of32 + i0) = make_float2(v0, v1);
                        *(float2*)(of32 + i1) = make_float2(v2, v3);
                        if (t < 0) { store_hilo(g_Hhi, g_Hlo, i0, v0, v1);
                                     store_hilo(g_Hhi, g_Hlo, i1, v2, v3); }
                        e[mi][ni][0] = v0; e[mi][ni][1] = v1;
                        e[mi][ni][2] = v2; e[mi][ni][3] = v3;
                    }
                if (do_gates || do_head) {
                    __syncthreads();
                    if (do_head)
                        frag2act<4>(e, sm, PARK_HI, PARK_LO, 0, m0w, n0e, lane);
                    if (do_gates) {
                        #pragma unroll
                        for (int mi = 0; mi < 2; mi++)
                            #pragma unroll
                            for (int ni = 0; ni < 4; ni++) {
                                int c = n0e + ni * 8 + t4 * 2;
                                size_t i0 = ((size_t)z * NN + gr0 + m0w + mi * 16 + g4) * DR + c;
                                size_t i1 = i0 + (size_t)8 * DR;
                                float2 g10 = *(const float2*)(g_G1 + i0);
                                float2 g11 = *(const float2*)(g_G1 + i1);
                                float2 h0 = *(const float2*)(g_H + i0);
                                float2 h1 = *(const float2*)(g_H + i1);
                                int r0 = m0w + mi * 16 + g4;
                                store_hilo(sm + ACT_HI, sm + ACT_LO,
                                           (size_t)r0 * AP2 + 64 + c,
                                           g10.x + (e[mi][ni][0] - h0.x),
                                           g10.y + (e[mi][ni][1] - h0.y));
                                store_hilo(sm + ACT_HI, sm + ACT_LO,
                                           (size_t)(r0 + 8) * AP2 + 64 + c,
                                           g11.x + (e[mi][ni][2] - h1.x),
                                           g11.y + (e[mi][ni][3] - h1.y));
                            }
                        const bf16* axh = g_AXhi + ((size_t)(t * BB + z) * NN + gr0) * DIN;
                        const bf16* axl = g_AXlo + ((size_t)(t * BB + z) * NN + gr0) * DIN;
                        #pragma unroll
                        for (int it = 0; it < 2; it++) {
                            int item = tid + it * 256, r = item >> 3, c = (item & 7) * 8;
                            *(uint4*)(sm + ACT_HI + (size_t)r * AP2 + c) =
                                *(const uint4*)(axh + (size_t)r * DIN + c);
                            *(uint4*)(sm + ACT_LO + (size_t)r * AP2 + c) =
                                *(const uint4*)(axl + (size_t)r * DIN + c);
                        }
                        float ez[2][4][4], er[2][4][4];
                        epi3dual(sm, sbase, 192,
                                 g_Whi + OWZ, g_Wlo + OWZ, g_Whi + OWR, g_Wlo + OWR,
                                 tid, lane, m0w, n0e, ez, er);
                        #pragma unroll
                        for (int mi = 0; mi < 2; mi++)
                            #pragma unroll
                            for (int ni = 0; ni < 4; ni++) {
                                int c = n0e + ni * 8 + t4 * 2;
                                float2 bz2 = *(const float2*)(bz + c);
                                float2 br2 = *(const float2*)(br + c);
                                size_t i0 = ((size_t)z * NN + gr0 + m0w + mi * 16 + g4) * DR + c;
                                size_t i1 = i0 + (size_t)8 * DR;
                                *(float2*)(g_Z + i0) =
                                    make_float2(sigm(ez[mi][ni][0] + bz2.x),
                                                sigm(ez[mi][ni][1] + bz2.y));
                                *(float2*)(g_Z + i1) =
                                    make_float2(sigm(ez[mi][ni][2] + bz2.x),
                                                sigm(ez[mi][ni][3] + bz2.y));
                                store_hilo(g_RHhi, g_RHlo, i0,
                                           sigm(er[mi][ni][0] + br2.x) * e[mi][ni][0],
                                           sigm(er[mi][ni][1] + br2.y) * e[mi][ni][1]);
                                store_hilo(g_RHhi, g_RHlo, i1,
                                           sigm(er[mi][ni][2] + br2.x) * e[mi][ni][2],
                                           sigm(er[mi][ni][3] + br2.y) * e[mi][ni][3]);
                            }
                    }
                    if (do_head) {
                        float e2[2][2][4];
                        epi3<2>(sm, sbase, PARK_HI, PARK_LO, 128, 72,
                                g_Whi + OWO, g_Wlo + OWO, 64, tid, lane, m0w, wn * 16, e2);
                        #pragma unroll
                        for (int mi = 0; mi < 2; mi++)
                            #pragma unroll
                            for (int ni = 0; ni < 2; ni++) {
                                int c = wn * 16 + ni * 8 + t4 * 2;
                                float2 bv = *(const float2*)(bo + c);
                                int r0 = gr0 + m0w + mi * 16 + g4;
                                size_t o0 = ((size_t)(z * (TT - 1) + t - 1) * NN + r0) * DIN + c;
                                size_t o1 = o0 + (size_t)8 * DIN;
                                *(float2*)(out + o0) =
                                    make_float2(e2[mi][ni][0] + bv.x, e2[mi][ni][1] + bv.y);
                                *(float2*)(out + o1) =
                                    make_float2(e2[mi][ni][2] + bv.x, e2[mi][ni][3] + bv.y);
                            }
                    }
                }
            } else {                              // p==3: H = blend
                frag2act<4>(acc, sm, ACT_HI, ACT_LO, 64, m0w, n0w, lane);
                const bf16* axh = g_AXhi + ((size_t)(t * BB + z) * NN + gr0) * DIN;
                const bf16* axl = g_AXlo + ((size_t)(t * BB + z) * NN + gr0) * DIN;
                #pragma unroll
                for (int it = 0; it < 2; it++) {
                    int item = tid + it * 256, r = item >> 3, c = (item & 7) * 8;
                    *(uint4*)(sm + ACT_HI + (size_t)r * AP2 + c) =
                        *(const uint4*)(axh + (size_t)r * DIN + c);
                    *(uint4*)(sm + ACT_LO + (size_t)r * AP2 + c) =
                        *(const uint4*)(axl + (size_t)r * DIN + c);
                }
                float e[2][4][4];
                epi3<4>(sm, sbase, ACT_HI, ACT_LO, 192, 136,
                        g_Whi + OWH, g_Wlo + OWH, 128, tid, lane, m0w, n0e, e);
                const float ob = g_OBS[t * BB + z];
                #pragma unroll
                for (int mi = 0; mi < 2; mi++)
                    #pragma unroll
                    for (int ni = 0; ni < 4; ni++) {
                        int c = n0e + ni * 8 + t4 * 2;
                        float2 bv = *(const float2*)(bh + c);
                        size_t i0 = ((size_t)z * NN + gr0 + m0w + mi * 16 + g4) * DR + c;
                        size_t i1 = i0 + (size_t)8 * DR;
                        float2 zz0 = *(const float2*)(g_Z + i0);
                        float2 zz1 = *(const float2*)(g_Z + i1);
                        float2 h0 = *(const float2*)(g_HV1 + i0);
                        float2 h1 = *(const float2*)(g_HV1 + i1);
                        float c0 = ftanh(e[mi][ni][0] + bv.x);
                        float c1 = ftanh(e[mi][ni][1] + bv.y);
                        float c2 = ftanh(e[mi][ni][2] + bv.x);
                        float c3 = ftanh(e[mi][ni][3] + bv.y);
                        float o0 = h0.x + (zz0.x * (c0 - h0.x)) * ob;
                        float o1 = h0.y + (zz0.y * (c1 - h0.y)) * ob;
                        float o2 = h1.x + (zz1.x * (c2 - h1.x)) * ob;
                        float o3 = h1.y + (zz1.y * (c3 - h1.y)) * ob;
                        *(float2*)(g_H + i0) = make_float2(o0, o1);
                        *(float2*)(g_H + i1) = make_float2(o2, o3);
                        store_hilo(g_Hhi, g_Hlo, i0, o0, o1);
                        store_hilo(g_Hhi, g_Hlo, i1, o2, o3);
                    }
            }
        }
    }
}

// --------------------------- small utility kernels -------------------------
__global__ void __launch_bounds__(256) convA_kernel(const float* __restrict__ A)
{
    const size_t r = blockIdx.x;
    const float* src = A + r * NN;
    bf16* dhi = g_Ahi + r * NN;
    bf16* dlo = g_Alo + r * NN;
    int i = threadIdx.x * 4;
    float4 v = *(const float4*)(src + i);
    float vv[4] = {v.x, v.y, v.z, v.w};
    #pragma unroll
    for (int j = 0; j < 4; j++) {
        bf16 h = __float2bfloat16(vv[j]);
        dhi[i+j] = h;
        dlo[i+j] = __float2bfloat16(vv[j] - __bfloat162float(h));
    }
}

__global__ void __launch_bounds__(256) convWall_kernel(
    const float* W0, const float* W1, const float* Wou, const float* Wz,
    const float* Wr, const float* Wh, const float* Wo)
{
    const float* W; long off; int n;
    switch (blockIdx.y) {
        case 0: W = W0;  off = OW0;   n = 16384; break;
        case 1: W = W1;  off = OW1;   n = 16384; break;
        case 2: W = Wou; off = OWOUT; n = 16384; break;
        case 3: W = Wz;  off = OWZ;   n = 24576; break;
        case 4: W = Wr;  off = OWR;   n = 24576; break;
        case 5: W = Wh;  off = OWH;   n = 24576; break;
        default: W = Wo; off = OWO;   n = 8192;  break;
    }
    int i = blockIdx.x * 256 + threadIdx.x;
    if (i >= n) return;
    float v = W[i];
    bf16 h = __float2bfloat16(v);
    g_Whi[off + i] = h;
    g_Wlo[off + i] = __float2bfloat16(v - __bfloat162float(h));
}

__global__ void __launch_bounds__(256) xmask_kernel(
    const float4* __restrict__ v, const float4* __restrict__ m)
{
    int i = blockIdx.x * 256 + threadIdx.x;
    float4 a = v[i], b = m[i];
    float x[4] = {a.x*b.x, a.y*b.y, a.z*b.z, a.w*b.w};
    bf16 hi[4], lo[4];
    #pragma unroll
    for (int j = 0; j < 4; j++) {
        hi[j] = __float2bfloat16(x[j]);
        lo[j] = __float2bfloat16(x[j] - __bfloat162float(hi[j]));
    }
    *(uint2*)&g_Xhi[(size_t)i*4] = *(uint2*)hi;
    *(uint2*)&g_Xlo[(size_t)i*4] = *(uint2*)lo;
}

__global__ void __launch_bounds__(256) inith_kernel(const float* __restrict__ h0)
{
    int i = blockIdx.x * 256 + threadIdx.x;
    float v = h0[i & (DR - 1)];
    g_H[i] = v;
    bf16 h = __float2bfloat16(v);
    g_Hhi[i] = h;
    g_Hlo[i] = __float2bfloat16(v - __bfloat162float(h));
    if (i == 0) g_bar = 0u;
}

__global__ void __launch_bounds__(256) obs_kernel(const float* __restrict__ masks)
{
    __shared__ float sh[256];
    int bt = blockIdx.x;
    const float* p = masks + (size_t)bt * (NN * DIN);
    float s = 0.f;
    for (int i = threadIdx.x; i < NN * DIN; i += 256) s += fabsf(p[i]);
    sh[threadIdx.x] = s; __syncthreads();
    for (int o = 128; o > 0; o >>= 1) {
        if (threadIdx.x < o) sh[threadIdx.x] += sh[threadIdx.x + o];
        __syncthreads();
    }
    if (threadIdx.x == 0) {
        int b = bt >> 5, t = bt & 31;
        g_OBS[t * BB + b] = (sh[0] > 1e-4f) ? 1.f : 0.f;
    }
}

// ------------------------------- launch ------------------------------------
extern "C" void kernel_launch(void* const* d_in, const int* in_sizes, int n_in,
                              void* d_out, int out_size)
{
    const float* values = (const float*)d_in[0];
    const float* masks  = (const float*)d_in[1];
    const float* A      = (const float*)d_in[2];
    const float* h0     = (const float*)d_in[3];
    const float* W0  = (const float*)d_in[4];  const float* b0v = (const float*)d_in[5];
    const float* W1  = (const float*)d_in[6];  const float* b1v = (const float*)d_in[7];
    const float* Wou = (const float*)d_in[8];  const float* bou = (const float*)d_in[9];
    const float* Wz  = (const float*)d_in[10]; const float* bz  = (const float*)d_in[11];
    const float* Wr  = (const float*)d_in[12]; const float* br  = (const float*)d_in[13];
    const float* Wh  = (const float*)d_in[14]; const float* bh  = (const float*)d_in[15];
    const float* Wo  = (const float*)d_in[16]; const float* bo  = (const float*)d_in[17];
    float* out = (float*)d_out;

    bf16 *Xhi, *Xlo;
    cudaGetSymbolAddress((void**)&Xhi, g_Xhi);
    cudaGetSymbolAddress((void**)&Xlo, g_Xlo);

    const int SMP  = 172032;                           // persist: max(mainloop, epi)
    const int SM64 = 3 * (2*64*72 + 2*64*72) * 2;      // 110592 B
    cudaFuncSetAttribute(persist_kernel, cudaFuncAttributeMaxDynamicSharedMemorySize, SMP);
    cudaFuncSetAttribute(ax_kernel, cudaFuncAttributeMaxDynamicSharedMemorySize, SM64);

    convA_kernel<<<BB*NN, 256>>>(A);
    convWall_kernel<<<dim3(96, 7), 256>>>(W0, W1, Wou, Wz, Wr, Wh, Wo);
    xmask_kernel<<<(BB*TT*NN*DIN)/4/256, 256>>>(
        (const float4*)values, (const float4*)masks);
    obs_kernel<<<BB*TT, 256>>>(masks);
    inith_kernel<<<(BB*NN*DR)/256, 256>>>(h0);
    ax_kernel<<<dim3(16, 1, BB*TT), 256, SM64>>>(Xhi, Xlo);
    persist_kernel<<<128, 256, SMP>>>(b0v, b1v, bou, bz, br, bh, bo, out);
}

// round 17
// speedup vs baseline: 1.0088x; 1.0088x over previous
#include <cuda_runtime.h>
#include <cuda_bf16.h>
#include <cstdint>
#include <math.h>

#define BB 8
#define TT 32
#define NN 1024
#define DIN 64
#define DR 128
#define DT_C 0.25f
typedef __nv_bfloat16 bf16;

#define OW0 0
#define OW1 16384
#define OWOUT 32768
#define OWZ 49152
#define OWR 73728
#define OWH 98304
#define OWO 122880

// ------------------------- device scratch (no allocs) ----------------------
__device__ bf16 g_Ahi[(size_t)BB*NN*NN];
__device__ bf16 g_Alo[(size_t)BB*NN*NN];
__device__ bf16 g_Xhi[(size_t)BB*TT*NN*DIN];
__device__ bf16 g_Xlo[(size_t)BB*TT*NN*DIN];
__device__ bf16 g_AXhi[(size_t)TT*BB*NN*DIN];
__device__ bf16 g_AXlo[(size_t)TT*BB*NN*DIN];
__device__ float g_H[BB*NN*DR];
__device__ bf16 g_Hhi[BB*NN*DR], g_Hlo[BB*NN*DR];
__device__ float g_HV1[BB*NN*DR];
__device__ float g_G1[BB*NN*DR];
__device__ bf16 g_Uahi[BB*NN*DR], g_Ualo[BB*NN*DR];
__device__ bf16 g_Ubhi[BB*NN*DR], g_Ublo[BB*NN*DR];
__device__ bf16 g_RHhi[BB*NN*DR], g_RHlo[BB*NN*DR];
__device__ float g_Z[BB*NN*DR];
__device__ float g_OBS[TT*BB];
__device__ bf16 g_Whi[131072], g_Wlo[131072];
__device__ unsigned g_barz[BB];

// ----------------------------- PTX helpers ---------------------------------
__device__ __forceinline__ unsigned smem_u32(const void* p) {
    unsigned a;
    asm("{ .reg .u64 t; cvta.to.shared.u64 t, %1; cvt.u32.u64 %0, t; }"
        : "=r"(a) : "l"(p));
    return a;
}
__device__ __forceinline__ void ldm_x4(unsigned& r0, unsigned& r1,
                                       unsigned& r2, unsigned& r3, unsigned a) {
    asm volatile("ldmatrix.sync.aligned.m8n8.x4.shared.b16 {%0,%1,%2,%3}, [%4];"
                 : "=r"(r0), "=r"(r1), "=r"(r2), "=r"(r3) : "r"(a));
}
__device__ __forceinline__ void ldm_x2t(unsigned& r0, unsigned& r1, unsigned a) {
    asm volatile("ldmatrix.sync.aligned.m8n8.x2.trans.shared.b16 {%0,%1}, [%2];"
                 : "=r"(r0), "=r"(r1) : "r"(a));
}
__device__ __forceinline__ void ldm_x4t(unsigned& r0, unsigned& r1,
                                        unsigned& r2, unsigned& r3, unsigned a) {
    asm volatile("ldmatrix.sync.aligned.m8n8.x4.trans.shared.b16 {%0,%1,%2,%3}, [%4];"
                 : "=r"(r0), "=r"(r1), "=r"(r2), "=r"(r3) : "r"(a));
}
__device__ __forceinline__ void mma_bf16(float* c, const unsigned* A, const unsigned* B) {
    asm volatile(
        "mma.sync.aligned.m16n8k16.row.col.f32.bf16.bf16.f32 "
        "{%0,%1,%2,%3}, {%4,%5,%6,%7}, {%8,%9}, {%0,%1,%2,%3};"
        : "+f"(c[0]), "+f"(c[1]), "+f"(c[2]), "+f"(c[3])
        : "r"(A[0]), "r"(A[1]), "r"(A[2]), "r"(A[3]), "r"(B[0]), "r"(B[1]));
}
__device__ __forceinline__ void cp16(unsigned s, const void* g) {
    asm volatile("cp.async.cg.shared.global [%0], [%1], 16;" :: "r"(s), "l"(g));
}
__device__ __forceinline__ void cp_commit() { asm volatile("cp.async.commit_group;"); }
template<int N> __device__ __forceinline__ void cp_wait() {
    asm volatile("cp.async.wait_group %0;" :: "n"(N));
}
__device__ __forceinline__ void store_hilo(bf16* hi, bf16* lo, size_t idx,
                                           float a, float b) {
    __nv_bfloat162 h = __floats2bfloat162_rn(a, b);
    *(unsigned*)(hi + idx) = *reinterpret_cast<unsigned*>(&h);
    __nv_bfloat162 l = __floats2bfloat162_rn(a - __bfloat162float(h.x),
                                             b - __bfloat162float(h.y));
    *(unsigned*)(lo + idx) = *reinterpret_cast<unsigned*>(&l);
}
__device__ __forceinline__ float sigm(float x) {
    return __fdividef(1.f, 1.f + __expf(-x));
}
__device__ __forceinline__ float ftanh(float x) {
    return 1.f - __fdividef(2.f, __expf(2.f * x) + 1.f);
}
// per-z grid barrier: release-arrive, tid0 spins, acquire, CTA release.
__device__ __forceinline__ void grid_bar(unsigned* ctr, unsigned target, int tid) {
    __syncthreads();
    if (tid == 0) {
        __threadfence();
        atomicAdd(ctr, 1u);
        while (*(volatile unsigned*)ctr < target)
            asm volatile("nanosleep.u32 64;");
        __threadfence();
    }
    __syncthreads();
}

// epilogue smem layout (bf16 elements)
#define AP2 200
#define ACT_HI 0
#define ACT_LO 12800
#define WBOFF 25600
#define WBSZ 17408
#define PARK_HI 60416
#define PARK_LO 73216

// pipelined single-W epilogue GEMM (3-product, 2 W buffers)
template<int NBE>
__device__ __forceinline__ void epi3(
    bf16* sm, unsigned sbase, int aHi, int aLo, int Kd, int WP,
    const bf16* Whi, const bf16* Wlo, int Dout,
    int tid, int lane, int m0w, int n0e, float (&e)[2][NBE][4])
{
    #pragma unroll
    for (int i = 0; i < 2; i++)
        #pragma unroll
        for (int j = 0; j < NBE; j++)
            #pragma unroll
            for (int q = 0; q < 4; q++) e[i][j][q] = 0.f;
    const int du4 = Dout / 8;
    auto stW = [&](int k0, int wb) {
        const int base = WBOFF + wb * WBSZ;
        for (int it = tid; it < 64 * du4; it += 256) {
            int r = it / du4, c = (it % du4) * 8;
            cp16(sbase + 2u * (base + r * WP + c), Whi + (size_t)(k0 + r) * Dout + c);
            cp16(sbase + 2u * (base + 64 * WP + r * WP + c),
                 Wlo + (size_t)(k0 + r) * Dout + c);
        }
        cp_commit();
    };
    const int NC = Kd / 64;
    __syncthreads();
    stW(0, 0);
    for (int c = 0; c < NC; c++) {
        cp_wait<0>();
        __syncthreads();
        if (c + 1 < NC) stW((c + 1) * 64, (c + 1) & 1);
        const int wb = WBOFF + (c & 1) * WBSZ;
        const int wl = wb + 64 * WP;
        #pragma unroll
        for (int ks = 0; ks < 4; ks++) {
            const int kk = ks * 16;
            unsigned ah[2][4], al[2][4];
            #pragma unroll
            for (int mi = 0; mi < 2; mi++) {
                unsigned row = m0w + mi * 16 + (lane & 15);
                unsigned col = c * 64 + kk + (lane >> 4) * 8;
                ldm_x4(ah[mi][0], ah[mi][1], ah[mi][2], ah[mi][3],
                       sbase + 2u * (aHi + row * AP2 + col));
                ldm_x4(al[mi][0], al[mi][1], al[mi][2], al[mi][3],
                       sbase + 2u * (aLo + row * AP2 + col));
            }
            unsigned bh[NBE][2], bl[NBE][2];
            if constexpr (NBE >= 2) {
                #pragma unroll
                for (int ni = 0; ni < NBE; ni += 2) {
                    unsigned row = kk + (lane & 15);
                    unsigned col = n0e + ni * 8 + (lane >> 4) * 8;
                    ldm_x4t(bh[ni][0], bh[ni][1], bh[ni+1][0], bh[ni+1][1],
                            sbase + 2u * (wb + row * WP + col));
                    ldm_x4t(bl[ni][0], bl[ni][1], bl[ni+1][0], bl[ni+1][1],
                            sbase + 2u * (wl + row * WP + col));
                }
            } else {
                unsigned row = kk + (lane & 15);
                ldm_x2t(bh[0][0], bh[0][1], sbase + 2u * (wb + row * WP + n0e));
                ldm_x2t(bl[0][0], bl[0][1], sbase + 2u * (wl + row * WP + n0e));
            }
            #pragma unroll
            for (int mi = 0; mi < 2; mi++)
                #pragma unroll
                for (int ni = 0; ni < NBE; ni++) {
                    mma_bf16(e[mi][ni], ah[mi], bh[ni]);
                    mma_bf16(e[mi][ni], ah[mi], bl[ni]);
                    mma_bf16(e[mi][ni], al[mi], bh[ni]);
                }
        }
    }
}

// dual-W epilogue GEMM (Z and R gates share the act tile; Dout=128)
__device__ __forceinline__ void epi3dual(
    bf16* sm, unsigned sbase, int Kd,
    const bf16* W0h, const bf16* W0l, const bf16* W1h, const bf16* W1l,
    int tid, int lane, int m0w, int n0e,
    float (&e0)[2][4][4], float (&e1)[2][4][4])
{
    #pragma unroll
    for (int i = 0; i < 2; i++)
        #pragma unroll
        for (int j = 0; j < 4; j++)
            #pragma unroll
            for (int q = 0; q < 4; q++) { e0[i][j][q] = 0.f; e1[i][j][q] = 0.f; }
    constexpr int WP = 136;
    auto stW = [&](const bf16* Whi, const bf16* Wlo, int k0, int wb) {
        const int base = WBOFF + wb * WBSZ;
        for (int it = tid; it < 64 * 16; it += 256) {
            int r = it / 16, c = (it % 16) * 8;
            cp16(sbase + 2u * (base + r * WP + c), Whi + (size_t)(k0 + r) * 128 + c);
            cp16(sbase + 2u * (base + 64 * WP + r * WP + c),
                 Wlo + (size_t)(k0 + r) * 128 + c);
        }
    };
    const int NC = Kd / 64;
    for (int c = 0; c < NC; c++) {
        __syncthreads();
        stW(W0h, W0l, c * 64, 0);
        stW(W1h, W1l, c * 64, 1);
        cp_commit();
        cp_wait<0>();
        __syncthreads();
        #pragma unroll
        for (int ks = 0; ks < 4; ks++) {
            const int kk = ks * 16;
            unsigned ah[2][4], al[2][4];
            #pragma unroll
            for (int mi = 0; mi < 2; mi++) {
                unsigned row = m0w + mi * 16 + (lane & 15);
                unsigned col = c * 64 + kk + (lane >> 4) * 8;
                ldm_x4(ah[mi][0], ah[mi][1], ah[mi][2], ah[mi][3],
                       sbase + 2u * (ACT_HI + row * AP2 + col));
                ldm_x4(al[mi][0], al[mi][1], al[mi][2], al[mi][3],
                       sbase + 2u * (ACT_LO + row * AP2 + col));
            }
            #pragma unroll
            for (int w = 0; w < 2; w++) {
                const int wb = WBOFF + w * WBSZ, wl = wb + 64 * WP;
                unsigned bh[4][2], bl[4][2];
                #pragma unroll
                for (int ni = 0; ni < 4; ni += 2) {
                    unsigned row = kk + (lane & 15);
                    unsigned col = n0e + ni * 8 + (lane >> 4) * 8;
                    ldm_x4t(bh[ni][0], bh[ni][1], bh[ni+1][0], bh[ni+1][1],
                            sbase + 2u * (wb + row * WP + col));
                    ldm_x4t(bl[ni][0], bl[ni][1], bl[ni+1][0], bl[ni+1][1],
                            sbase + 2u * (wl + row * WP + col));
                }
                #pragma unroll
                for (int mi = 0; mi < 2; mi++)
                    #pragma unroll
                    for (int ni = 0; ni < 4; ni++) {
                        float* ee = w ? e1[mi][ni] : e0[mi][ni];
                        mma_bf16(ee, ah[mi], bh[ni]);
                        mma_bf16(ee, ah[mi], bl[ni]);
                        mma_bf16(ee, al[mi], bh[ni]);
                    }
            }
        }
    }
}

template<int NBX>
__device__ __forceinline__ void frag2act(const float (&a)[2][NBX][4], bf16* sm,
                                         int hiOff, int loOff, int goff,
                                         int m0, int n0, int lane)
{
    const int g4 = lane >> 2, t4 = lane & 3;
    #pragma unroll
    for (int mi = 0; mi < 2; mi++)
        #pragma unroll
        for (int ni = 0; ni < NBX; ni++) {
            int r0 = m0 + mi * 16 + g4;
            int c  = goff + n0 + ni * 8 + t4 * 2;
            store_hilo(sm + hiOff, sm + loOff, (size_t)r0 * AP2 + c,
                       a[mi][ni][0], a[mi][ni][1]);
            store_hilo(sm + hiOff, sm + loOff, (size_t)(r0 + 8) * AP2 + c,
                       a[mi][ni][2], a[mi][ni][3]);
        }
}

// ---------------------------------------------------------------------------
// ax_kernel: AX[t,b] = A[b] @ X[b,t], bf16 hi/lo out.  grid (16,1,BB*TT)
// ---------------------------------------------------------------------------
__global__ void __launch_bounds__(256) ax_kernel(
    const bf16* __restrict__ Bhi_g, const bf16* __restrict__ Blo_g)
{
    constexpr int DN = 64;
    constexpr int AP = 72, BP = DN + 8, NB = 2;
    constexpr int A_LO = 64 * AP;
    constexpr int B_OFF = 2 * 64 * AP;
    constexpr int B_LO  = B_OFF + 64 * BP;
    constexpr int SBUF  = 2 * 64 * AP + 2 * 64 * BP;

    extern __shared__ bf16 sm[];
    const unsigned sbase = smem_u32(sm);
    const int tid = threadIdx.x, wid = tid >> 5, lane = tid & 31;
    const int mt = blockIdx.x;
    const int z  = blockIdx.z;
    const int a_idx = z / TT;
    const int cz = (z % TT) * BB + a_idx;
    const bf16* Bhi = Bhi_g + (size_t)z * NN * DN;
    const bf16* Blo = Blo_g + (size_t)z * NN * DN;
    const bf16* Ahi = g_Ahi + ((size_t)a_idx * NN + (size_t)mt * 64) * NN;
    const bf16* Alo = g_Alo + ((size_t)a_idx * NN + (size_t)mt * 64) * NN;
    const int wm = wid >> 2, wn = wid & 3;
    const int m0w = wm * 32, n0w = wn * (DN / 4);

    auto stage = [&](int ch, int buf) {
        const int k0 = ch * 64;
        const unsigned db = sbase + 2u * (unsigned)(buf * SBUF);
        #pragma unroll
        for (int it = 0; it < 2; it++) {
            int item = tid + it * 256, r = item >> 3, c = item & 7;
            cp16(db + 2u * (r * AP + c * 8),        Ahi + (size_t)r * NN + k0 + c * 8);
            cp16(db + 2u * (A_LO + r * AP + c * 8), Alo + (size_t)r * NN + k0 + c * 8);
        }
        #pragma unroll
        for (int it = 0; it < 2; it++) {
            int item = tid + it * 256, r = item / 8, c = item % 8;
            cp16(db + 2u * (B_OFF + r * BP + c * 8), Bhi + (size_t)(k0 + r) * DN + c * 8);
            cp16(db + 2u * (B_LO  + r * BP + c * 8), Blo + (size_t)(k0 + r) * DN + c * 8);
        }
        cp_commit();
    };

    float acc[2][NB][4];
    #pragma unroll
    for (int i = 0; i < 2; i++)
        #pragma unroll
        for (int j = 0; j < NB; j++)
            #pragma unroll
            for (int q = 0; q < 4; q++) acc[i][j][q] = 0.f;

    stage(0, 0); stage(1, 1);
    for (int ch = 0; ch < 16; ch++) {
        const int buf = ch % 3;
        if (ch < 15) cp_wait<1>(); else cp_wait<0>();
        __syncthreads();
        if (ch <= 13) stage(ch + 2, (ch + 2) % 3);
        const unsigned aB = sbase + 2u * (unsigned)(buf * SBUF);
        #pragma unroll
        for (int ks = 0; ks < 4; ks++) {
            const int kk = ks * 16;
            unsigned ah[2][4], al[2][4];
            #pragma unroll
            for (int mi = 0; mi < 2; mi++) {
                unsigned row = m0w + mi * 16 + (lane & 15);
                unsigned col = kk + (lane >> 4) * 8;
                ldm_x4(ah[mi][0], ah[mi][1], ah[mi][2], ah[mi][3],
                       aB + 2u * (row * AP + col));
                ldm_x4(al[mi][0], al[mi][1], al[mi][2], al[mi][3],
                       aB + 2u * (A_LO + row * AP + col));
            }
            unsigned bh[NB][2], bl[NB][2];
            {
                unsigned row = kk + (lane & 15);
                unsigned col = n0w + (lane >> 4) * 8;
                ldm_x4t(bh[0][0], bh[0][1], bh[1][0], bh[1][1],
                        aB + 2u * (B_OFF + row * BP + col));
                ldm_x4t(bl[0][0], bl[0][1], bl[1][0], bl[1][1],
                        aB + 2u * (B_LO + row * BP + col));
            }
            #pragma unroll
            for (int mi = 0; mi < 2; mi++)
                #pragma unroll
                for (int ni = 0; ni < NB; ni++) {
                    mma_bf16(acc[mi][ni], ah[mi], bh[ni]);
                    mma_bf16(acc[mi][ni], ah[mi], bl[ni]);
                    mma_bf16(acc[mi][ni], al[mi], bh[ni]);
                }
        }
    }
    const int g4 = lane >> 2, t4 = lane & 3;
    bf16* ohi = g_AXhi + (size_t)cz * NN * DIN;
    bf16* olo = g_AXlo + (size_t)cz * NN * DIN;
    #pragma unroll
    for (int mi = 0; mi < 2; mi++)
        #pragma unroll
        for (int ni = 0; ni < NB; ni++) {
            int r0 = mt * 64 + m0w + mi * 16 + g4;
            int c  = n0w + ni * 8 + t4 * 2;
            store_hilo(ohi, olo, (size_t)r0 * DN + c, acc[mi][ni][0], acc[mi][ni][1]);
            store_hilo(ohi, olo, (size_t)(r0 + 8) * DN + c, acc[mi][ni][2], acc[mi][ni][3]);
        }
}

// ---------------------------------------------------------------------------
// persist_kernel: all 130 recurrence phases, grid 128 CTAs, per-z barriers
// (8 independent batch chains of 16 CTAs each).
// ---------------------------------------------------------------------------
__global__ void __launch_bounds__(256) persist_kernel(
    const float* __restrict__ b0v, const float* __restrict__ b1v,
    const float* __restrict__ bou, const float* __restrict__ bz,
    const float* __restrict__ br,  const float* __restrict__ bh,
    const float* __restrict__ bo,  float* __restrict__ out)
{
    constexpr int DN = 128;
    constexpr int AP = 72, BP = DN + 8, NB = 4;
    constexpr int A_LO = 64 * AP;
    constexpr int B_OFF = 2 * 64 * AP;
    constexpr int B_LO  = B_OFF + 64 * BP;
    constexpr int SBUF  = 2 * 64 * AP + 2 * 64 * BP;

    extern __shared__ bf16 sm[];
    const unsigned sbase = smem_u32(sm);
    const int tid = threadIdx.x, wid = tid >> 5, lane = tid & 31;
    const int mt = blockIdx.x & 15;
    const int z  = blockIdx.x >> 4;
    const bf16* Ahi = g_Ahi + ((size_t)z * NN + (size_t)mt * 64) * NN;
    const bf16* Alo = g_Alo + ((size_t)z * NN + (size_t)mt * 64) * NN;
    const int wm = wid >> 2, wn = wid & 3;
    const int m0w = wm * 32, n0w = wn * 32;
    const int g4 = lane >> 2, t4 = lane & 3;
    const int gr0 = mt * 64;
    const int n0e = wn * 32;
    unsigned* barz = &g_barz[z];
    unsigned ph = 0;

    auto stageA = [&](int ch, int buf) {
        const int k0 = ch * 64;
        const unsigned db = sbase + 2u * (unsigned)(buf * SBUF);
        #pragma unroll
        for (int it = 0; it < 2; it++) {
            int item = tid + it * 256, r = item >> 3, c = item & 7;
            cp16(db + 2u * (r * AP + c * 8),        Ahi + (size_t)r * NN + k0 + c * 8);
            cp16(db + 2u * (A_LO + r * AP + c * 8), Alo + (size_t)r * NN + k0 + c * 8);
        }
    };

    for (int k = 0; k < 33; k++) {
        const int t = k - 1;
        for (int p = 0; p < 4; p++) {
            if (p == 3 && !(t >= 0 && t < TT - 1)) break;
            const bf16 *Bhi, *Blo;
            if (p == 0)      { Bhi = g_Hhi;  Blo = g_Hlo;  }
            else if (p == 1) { Bhi = g_Uahi; Blo = g_Ualo; }
            else if (p == 2) { Bhi = g_Ubhi; Blo = g_Ublo; }
            else             { Bhi = g_RHhi; Blo = g_RHlo; }
            Bhi += (size_t)z * NN * DN;
            Blo += (size_t)z * NN * DN;

            auto stageB = [&](int ch, int buf) {
                const int k0 = ch * 64;
                const unsigned db = sbase + 2u * (unsigned)(buf * SBUF);
                #pragma unroll
                for (int it = 0; it < 4; it++) {
                    int item = tid + it * 256, r = item / 16, c = item % 16;
                    cp16(db + 2u * (B_OFF + r * BP + c * 8),
                         Bhi + (size_t)(k0 + r) * DN + c * 8);
                    cp16(db + 2u * (B_LO + r * BP + c * 8),
                         Blo + (size_t)(k0 + r) * DN + c * 8);
                }
            };

            float acc[2][NB][4];
            #pragma unroll
            for (int i = 0; i < 2; i++)
                #pragma unroll
                for (int j = 0; j < NB; j++)
                    #pragma unroll
                    for (int q = 0; q < 4; q++) acc[i][j][q] = 0.f;

            __syncthreads();                      // epi smem reuse guard
            stageA(0, 0);
            stageA(1, 1);
            grid_bar(barz, (++ph) * 16u, tid);    // z-chain: B operand valid
            stageB(0, 0); cp_commit();
            stageB(1, 1); cp_commit();

            for (int ch = 0; ch < 16; ch++) {
                const int buf = ch % 3;
                if (ch < 15) cp_wait<1>(); else cp_wait<0>();
                __syncthreads();
                if (ch <= 13) { stageA(ch + 2, (ch + 2) % 3);
                                stageB(ch + 2, (ch + 2) % 3); cp_commit(); }
                const unsigned aB = sbase + 2u * (unsigned)(buf * SBUF);
                #pragma unroll
                for (int ks = 0; ks < 4; ks++) {
                    const int kk = ks * 16;
                    unsigned ah[2][4], al[2][4];
                    #pragma unroll
                    for (int mi = 0; mi < 2; mi++) {
                        unsigned row = m0w + mi * 16 + (lane & 15);
                        unsigned col = kk + (lane >> 4) * 8;
                        ldm_x4(ah[mi][0], ah[mi][1], ah[mi][2], ah[mi][3],
                               aB + 2u * (row * AP + col));
                        ldm_x4(al[mi][0], al[mi][1], al[mi][2], al[mi][3],
                               aB + 2u * (A_LO + row * AP + col));
                    }
                    unsigned bhx[NB][2], blx[NB][2];
                    #pragma unroll
                    for (int ni = 0; ni < NB; ni += 2) {
                        unsigned row = kk + (lane & 15);
                        unsigned col = n0w + ni * 8 + (lane >> 4) * 8;
                        ldm_x4t(bhx[ni][0], bhx[ni][1], bhx[ni+1][0], bhx[ni+1][1],
                                aB + 2u * (B_OFF + row * BP + col));
                        ldm_x4t(blx[ni][0], blx[ni][1], blx[ni+1][0], blx[ni+1][1],
                                aB + 2u * (B_LO + row * BP + col));
                    }
                    #pragma unroll
                    for (int mi = 0; mi < 2; mi++)
                        #pragma unroll
                        for (int ni = 0; ni < NB; ni++) {
                            mma_bf16(acc[mi][ni], ah[mi], bhx[ni]);
                            mma_bf16(acc[mi][ni], ah[mi], blx[ni]);
                            mma_bf16(acc[mi][ni], al[mi], bhx[ni]);
                        }
                }
            }
            __syncthreads();                      // stage buffers dead

            // ---------------- epilogue ----------------
            if (p <= 1) {                         // U' = tanh(G@W + b)
                if (p == 0) {                     // also persist G1 = A@H
                    #pragma unroll
                    for (int mi = 0; mi < 2; mi++)
                        #pragma unroll
                        for (int ni = 0; ni < 4; ni++) {
                            int c = n0w + ni * 8 + t4 * 2;
                            size_t i0 = ((size_t)z * NN + gr0 + m0w + mi * 16 + g4) * DR + c;
                            *(float2*)(g_G1 + i0) = make_float2(acc[mi][ni][0], acc[mi][ni][1]);
                            *(float2*)(g_G1 + i0 + (size_t)8 * DR) =
                                make_float2(acc[mi][ni][2], acc[mi][ni][3]);
                        }
                }
                frag2act<4>(acc, sm, ACT_HI, ACT_LO, 0, m0w, n0w, lane);
                float e[2][4][4];
                epi3<4>(sm, sbase, ACT_HI, ACT_LO, 128, 136,
                        g_Whi + (p == 0 ? OW0 : OW1), g_Wlo + (p == 0 ? OW0 : OW1),
                        128, tid, lane, m0w, n0e, e);
                const float* bb = (p == 0) ? b0v : b1v;
                bf16* ohi = (p == 0) ? g_Uahi : g_Ubhi;
                bf16* olo = (p == 0) ? g_Ualo : g_Ublo;
                #pragma unroll
                for (int mi = 0; mi < 2; mi++)
                    #pragma unroll
                    for (int ni = 0; ni < 4; ni++) {
                        int c = n0e + ni * 8 + t4 * 2;
                        float2 bv = *(const float2*)(bb + c);
                        size_t i0 = ((size_t)z * NN + gr0 + m0w + mi * 16 + g4) * DR + c;
                        size_t i1 = i0 + (size_t)8 * DR;
                        store_hilo(ohi, olo, i0, ftanh(e[mi][ni][0] + bv.x),
                                               ftanh(e[mi][ni][1] + bv.y));
                        store_hilo(ohi, olo, i1, ftanh(e[mi][ni][2] + bv.x),
                                               ftanh(e[mi][ni][3] + bv.y));
                    }
            } else if (p == 2) {                  // HV1 + gates + head
                const bool do_gates = (t >= 0 && t < TT - 1);
                const bool do_head  = (t >= 1);
                float* of32 = (t < 0) ? g_H : g_HV1;
                frag2act<4>(acc, sm, ACT_HI, ACT_LO, 0, m0w, n0w, lane);
                float e[2][4][4];
                epi3<4>(sm, sbase, ACT_HI, ACT_LO, 128, 136,
                        g_Whi + OWOUT, g_Wlo + OWOUT, 128, tid, lane, m0w, n0e, e);
                #pragma unroll
                for (int mi = 0; mi < 2; mi++)
                    #pragma unroll
                    for (int ni = 0; ni < 4; ni++) {
                        int c = n0e + ni * 8 + t4 * 2;
                        float2 bv = *(const float2*)(bou + c);
                        size_t i0 = ((size_t)z * NN + gr0 + m0w + mi * 16 + g4) * DR + c;
                        size_t i1 = i0 + (size_t)8 * DR;
                        float2 h0 = *(const float2*)(g_H + i0);
                        float2 h1 = *(const float2*)(g_H + i1);
                        float v0 = h0.x + (e[mi][ni][0] + bv.x) * DT_C;
                        float v1 = h0.y + (e[mi][ni][1] + bv.y) * DT_C;
                        float v2 = h1.x + (e[mi][ni][2] + bv.x) * DT_C;
                        float v3 = h1.y + (e[mi][ni][3] + bv.y) * DT_C;
                        *(float2*)(of32 + i0) = make_float2(v0, v1);
                        *(float2*)(of32 + i1) = make_float2(v2, v3);
                        if (t < 0) { store_hilo(g_Hhi, g_Hlo, i0, v0, v1);
                                     store_hilo(g_Hhi, g_Hlo, i1, v2, v3); }
                        e[mi][ni][0] = v0; e[mi][ni][1] = v1;
                        e[mi][ni][2] = v2; e[mi][ni][3] = v3;
                    }
                if (do_gates || do_head) {
                    __syncthreads();
                    if (do_head)
                        frag2act<4>(e, sm, PARK_HI, PARK_LO, 0, m0w, n0e, lane);
                    if (do_gates) {
                        #pragma unroll
                        for (int mi = 0; mi < 2; mi++)
                            #pragma unroll
                            for (int ni = 0; ni < 4; ni++) {
                                int c = n0e + ni * 8 + t4 * 2;
                                size_t i0 = ((size_t)z * NN + gr0 + m0w + mi * 16 + g4) * DR + c;
                                size_t i1 = i0 + (size_t)8 * DR;
                                float2 g10 = *(const float2*)(g_G1 + i0);
                                float2 g11 = *(const float2*)(g_G1 + i1);
                                float2 h0 = *(const float2*)(g_H + i0);
                                float2 h1 = *(const float2*)(g_H + i1);
                                int r0 = m0w + mi * 16 + g4;
                                store_hilo(sm + ACT_HI, sm + ACT_LO,
                                           (size_t)r0 * AP2 + 64 + c,
                                           g10.x + (e[mi][ni][0] - h0.x),
                                           g10.y + (e[mi][ni][1] - h0.y));
                                store_hilo(sm + ACT_HI, sm + ACT_LO,
                                           (size_t)(r0 + 8) * AP2 + 64 + c,
                                           g11.x + (e[mi][ni][2] - h1.x),
                                           g11.y + (e[mi][ni][3] - h1.y));
                            }
                        const bf16* axh = g_AXhi + ((size_t)(t * BB + z) * NN + gr0) * DIN;
                        const bf16* axl = g_AXlo + ((size_t)(t * BB + z) * NN + gr0) * DIN;
                        #pragma unroll
                        for (int it = 0; it < 2; it++) {
                            int item = tid + it * 256, r = item >> 3, c = (item & 7) * 8;
                            *(uint4*)(sm + ACT_HI + (size_t)r * AP2 + c) =
                                *(const uint4*)(axh + (size_t)r * DIN + c);
                            *(uint4*)(sm + ACT_LO + (size_t)r * AP2 + c) =
                                *(const uint4*)(axl + (size_t)r * DIN + c);
                        }
                        float ez[2][4][4], er[2][4][4];
                        epi3dual(sm, sbase, 192,
                                 g_Whi + OWZ, g_Wlo + OWZ, g_Whi + OWR, g_Wlo + OWR,
                                 tid, lane, m0w, n0e, ez, er);
                        #pragma unroll
                        for (int mi = 0; mi < 2; mi++)
                            #pragma unroll
                            for (int ni = 0; ni < 4; ni++) {
                                int c = n0e + ni * 8 + t4 * 2;
                                float2 bz2 = *(const float2*)(bz + c);
                                float2 br2 = *(const float2*)(br + c);
                                size_t i0 = ((size_t)z * NN + gr0 + m0w + mi * 16 + g4) * DR + c;
                                size_t i1 = i0 + (size_t)8 * DR;
                                *(float2*)(g_Z + i0) =
                                    make_float2(sigm(ez[mi][ni][0] + bz2.x),
                                                sigm(ez[mi][ni][1] + bz2.y));
                                *(float2*)(g_Z + i1) =
                                    make_float2(sigm(ez[mi][ni][2] + bz2.x),
                                                sigm(ez[mi][ni][3] + bz2.y));
                                store_hilo(g_RHhi, g_RHlo, i0,
                                           sigm(er[mi][ni][0] + br2.x) * e[mi][ni][0],
                                           sigm(er[mi][ni][1] + br2.y) * e[mi][ni][1]);
                                store_hilo(g_RHhi, g_RHlo, i1,
                                           sigm(er[mi][ni][2] + br2.x) * e[mi][ni][2],
                                           sigm(er[mi][ni][3] + br2.y) * e[mi][ni][3]);
                            }
                    }
                    if (do_head) {
                        float e2[2][2][4];
                        epi3<2>(sm, sbase, PARK_HI, PARK_LO, 128, 72,
                                g_Whi + OWO, g_Wlo + OWO, 64, tid, lane, m0w, wn * 16, e2);
                        #pragma unroll
                        for (int mi = 0; mi < 2; mi++)
                            #pragma unroll
                            for (int ni = 0; ni < 2; ni++) {
                                int c = wn * 16 + ni * 8 + t4 * 2;
                                float2 bv = *(const float2*)(bo + c);
                                int r0 = gr0 + m0w + mi * 16 + g4;
                                size_t o0 = ((size_t)(z * (TT - 1) + t - 1) * NN + r0) * DIN + c;
                                size_t o1 = o0 + (size_t)8 * DIN;
                                *(float2*)(out + o0) =
                                    make_float2(e2[mi][ni][0] + bv.x, e2[mi][ni][1] + bv.y);
                                *(float2*)(out + o1) =
                                    make_float2(e2[mi][ni][2] + bv.x, e2[mi][ni][3] + bv.y);
                            }
                    }
                }
            } else {                              // p==3: H = blend
                frag2act<4>(acc, sm, ACT_HI, ACT_LO, 64, m0w, n0w, lane);
                const bf16* axh = g_AXhi + ((size_t)(t * BB + z) * NN + gr0) * DIN;
                const bf16* axl = g_AXlo + ((size_t)(t * BB + z) * NN + gr0) * DIN;
                #pragma unroll
                for (int it = 0; it < 2; it++) {
                    int item = tid + it * 256, r = item >> 3, c = (item & 7) * 8;
                    *(uint4*)(sm + ACT_HI + (size_t)r * AP2 + c) =
                        *(const uint4*)(axh + (size_t)r * DIN + c);
                    *(uint4*)(sm + ACT_LO + (size_t)r * AP2 + c) =
                        *(const uint4*)(axl + (size_t)r * DIN + c);
                }
                float e[2][4][4];
                epi3<4>(sm, sbase, ACT_HI, ACT_LO, 192, 136,
                        g_Whi + OWH, g_Wlo + OWH, 128, tid, lane, m0w, n0e, e);
                const float ob = g_OBS[t * BB + z];
                #pragma unroll
                for (int mi = 0; mi < 2; mi++)
                    #pragma unroll
                    for (int ni = 0; ni < 4; ni++) {
                        int c = n0e + ni * 8 + t4 * 2;
                        float2 bv = *(const float2*)(bh + c);
                        size_t i0 = ((size_t)z * NN + gr0 + m0w + mi * 16 + g4) * DR + c;
                        size_t i1 = i0 + (size_t)8 * DR;
                        float2 zz0 = *(const float2*)(g_Z + i0);
                        float2 zz1 = *(const float2*)(g_Z + i1);
                        float2 h0 = *(const float2*)(g_HV1 + i0);
                        float2 h1 = *(const float2*)(g_HV1 + i1);
                        float c0 = ftanh(e[mi][ni][0] + bv.x);
                        float c1 = ftanh(e[mi][ni][1] + bv.y);
                        float c2 = ftanh(e[mi][ni][2] + bv.x);
                        float c3 = ftanh(e[mi][ni][3] + bv.y);
                        float o0 = h0.x + (zz0.x * (c0 - h0.x)) * ob;
                        float o1 = h0.y + (zz0.y * (c1 - h0.y)) * ob;
                        float o2 = h1.x + (zz1.x * (c2 - h1.x)) * ob;
                        float o3 = h1.y + (zz1.y * (c3 - h1.y)) * ob;
                        *(float2*)(g_H + i0) = make_float2(o0, o1);
                        *(float2*)(g_H + i1) = make_float2(o2, o3);
                        store_hilo(g_Hhi, g_Hlo, i0, o0, o1);
                        store_hilo(g_Hhi, g_Hlo, i1, o2, o3);
                    }
            }
        }
    }
}

// --------------------------- small utility kernels -------------------------
__global__ void __launch_bounds__(256) convA_kernel(const float* __restrict__ A)
{
    const size_t r = blockIdx.x;
    const float* src = A + r * NN;
    bf16* dhi = g_Ahi + r * NN;
    bf16* dlo = g_Alo + r * NN;
    int i = threadIdx.x * 4;
    float4 v = *(const float4*)(src + i);
    float vv[4] = {v.x, v.y, v.z, v.w};
    #pragma unroll
    for (int j = 0; j < 4; j++) {
        bf16 h = __float2bfloat16(vv[j]);
        dhi[i+j] = h;
        dlo[i+j] = __float2bfloat16(vv[j] - __bfloat162float(h));
    }
}

__global__ void __launch_bounds__(256) convWall_kernel(
    const float* W0, const float* W1, const float* Wou, const float* Wz,
    const float* Wr, const float* Wh, const float* Wo)
{
    const float* W; long off; int n;
    switch (blockIdx.y) {
        case 0: W = W0;  off = OW0;   n = 16384; break;
        case 1: W = W1;  off = OW1;   n = 16384; break;
        case 2: W = Wou; off = OWOUT; n = 16384; break;
        case 3: W = Wz;  off = OWZ;   n = 24576; break;
        case 4: W = Wr;  off = OWR;   n = 24576; break;
        case 5: W = Wh;  off = OWH;   n = 24576; break;
        default: W = Wo; off = OWO;   n = 8192;  break;
    }
    int i = blockIdx.x * 256 + threadIdx.x;
    if (i >= n) return;
    float v = W[i];
    bf16 h = __float2bfloat16(v);
    g_Whi[off + i] = h;
    g_Wlo[off + i] = __float2bfloat16(v - __bfloat162float(h));
}

__global__ void __launch_bounds__(256) xmask_kernel(
    const float4* __restrict__ v, const float4* __restrict__ m)
{
    int i = blockIdx.x * 256 + threadIdx.x;
    float4 a = v[i], b = m[i];
    float x[4] = {a.x*b.x, a.y*b.y, a.z*b.z, a.w*b.w};
    bf16 hi[4], lo[4];
    #pragma unroll
    for (int j = 0; j < 4; j++) {
        hi[j] = __float2bfloat16(x[j]);
        lo[j] = __float2bfloat16(x[j] - __bfloat162float(hi[j]));
    }
    *(uint2*)&g_Xhi[(size_t)i*4] = *(uint2*)hi;
    *(uint2*)&g_Xlo[(size_t)i*4] = *(uint2*)lo;
}

__global__ void __launch_bounds__(256) inith_kernel(const float* __restrict__ h0)
{
    int i = blockIdx.x * 256 + threadIdx.x;
    float v = h0[i & (DR - 1)];
    g_H[i] = v;
    bf16 h = __float2bfloat16(v);
    g_Hhi[i] = h;
    g_Hlo[i] = __float2bfloat16(v - __bfloat162float(h));
    if (i < BB) g_barz[i] = 0u;
}

__global__ void __launch_bounds__(256) obs_kernel(const float* __restrict__ masks)
{
    __shared__ float sh[256];
    int bt = blockIdx.x;
    const float* p = masks + (size_t)bt * (NN * DIN);
    float s = 0.f;
    for (int i = threadIdx.x; i < NN * DIN; i += 256) s += fabsf(p[i]);
    sh[threadIdx.x] = s; __syncthreads();
    for (int o = 128; o > 0; o >>= 1) {
        if (threadIdx.x < o) sh[threadIdx.x] += sh[threadIdx.x + o];
        __syncthreads();
    }
    if (threadIdx.x == 0) {
        int b = bt >> 5, t = bt & 31;
        g_OBS[t * BB + b] = (sh[0] > 1e-4f) ? 1.f : 0.f;
    }
}

// ------------------------------- launch ------------------------------------
extern "C" void kernel_launch(void* const* d_in, const int* in_sizes, int n_in,
                              void* d_out, int out_size)
{
    const float* values = (const float*)d_in[0];
    const float* masks  = (const float*)d_in[1];
    const float* A      = (const float*)d_in[2];
    const float* h0     = (const float*)d_in[3];
    const float* W0  = (const float*)d_in[4];  const float* b0v = (const float*)d_in[5];
    const float* W1  = (const float*)d_in[6];  const float* b1v = (const float*)d_in[7];
    const float* Wou = (const float*)d_in[8];  const float* bou = (const float*)d_in[9];
    const float* Wz  = (const float*)d_in[10]; const float* bz  = (const float*)d_in[11];
    const float* Wr  = (const float*)d_in[12]; const float* br  = (const float*)d_in[13];
    const float* Wh  = (const float*)d_in[14]; const float* bh  = (const float*)d_in[15];
    const float* Wo  = (const float*)d_in[16]; const float* bo  = (const float*)d_in[17];
    float* out = (float*)d_out;

    bf16 *Xhi, *Xlo;
    cudaGetSymbolAddress((void**)&Xhi, g_Xhi);
    cudaGetSymbolAddress((void**)&Xlo, g_Xlo);

    const int SMP  = 172032;                           // persist: max(mainloop, epi)
    const int SM64 = 3 * (2*64*72 + 2*64*72) * 2;      // 110592 B
    cudaFuncSetAttribute(persist_kernel, cudaFuncAttributeMaxDynamicSharedMemorySize, SMP);
    cudaFuncSetAttribute(ax_kernel, cudaFuncAttributeMaxDynamicSharedMemorySize, SM64);

    convA_kernel<<<BB*NN, 256>>>(A);
    convWall_kernel<<<dim3(96, 7), 256>>>(W0, W1, Wou, Wz, Wr, Wh, Wo);
    xmask_kernel<<<(BB*TT*NN*DIN)/4/256, 256>>>(
        (const float4*)values, (const float4*)masks);
    obs_kernel<<<BB*TT, 256>>>(masks);
    inith_kernel<<<(BB*NN*DR)/256, 256>>>(h0);
    ax_kernel<<<dim3(16, 1, BB*TT), 256, SM64>>>(Xhi, Xlo);
    persist_kernel<<<128, 256, SMP>>>(b0v, b1v, bou, bz, br, bh, bo, out);
}